// round 10
// baseline (speedup 1.0000x reference)
#include <cuda_runtime.h>
#include <cstdint>

// Problem constants (fixed for this instance):
//   logits:  [B=256, VOCAB=128000] float32
//   save_id: [B=256, HIST=512] int32 (JAX x64 disabled)
//   penalty_value: [1] float32
//   penalty_range: 64
#define B_DIM      256
#define VOCAB_DIM  128000
#define HIST_DIM   512
#define PEN_RANGE  64

// Flat tiling: 8,192,000 float4 total = 4000 tiles x 2048 float4.
// Each block: 256 threads x 8 float4 (128 B/thread, front-batched MLP=8).
#define THREADS       256
#define F4_PER_THREAD 8
#define TILE_F4       (THREADS * F4_PER_THREAD)   // 2048
#define TILE_FLOATS   (TILE_F4 * 4)               // 8192
#define NUM_TILES     4000                        // 8,192,000 / 2048 exact

// Fused copy + penalty fixup over flat tiles. A tile may straddle one row
// boundary, so fixup checks up to two rows' id lists (64 ids each):
// threads 0..63 handle the first row, 64..127 the second (if distinct).
__global__ void __launch_bounds__(THREADS)
apply_penalty_fused(const float4* __restrict__ logits4,
                    const float*  __restrict__ logits,
                    const int*    __restrict__ save_id,
                    const float*  __restrict__ penalty,
                    float4* __restrict__ out4,
                    float*  __restrict__ out) {
    const int b = blockIdx.x;

    // ---- copy phase: 8 batched loads, then 8 stores ----
    const size_t base4 = (size_t)b * TILE_F4 + threadIdx.x;
    float4 v[F4_PER_THREAD];
    #pragma unroll
    for (int i = 0; i < F4_PER_THREAD; i++)
        v[i] = logits4[base4 + (size_t)i * THREADS];
    #pragma unroll
    for (int i = 0; i < F4_PER_THREAD; i++)
        out4[base4 + (size_t)i * THREADS] = v[i];

    __syncthreads();   // copy stores ordered before fixup stores (block scope)

    // ---- fixup phase ----
    const size_t lo = (size_t)b * TILE_FLOATS;          // first float of tile
    const size_t hi = lo + TILE_FLOATS;                 // one past last
    const int r0 = (int)(lo / VOCAB_DIM);
    const int r1 = (int)((hi - 1) / VOCAB_DIM);         // r0 or r0+1

    if (threadIdx.x < 2 * PEN_RANGE) {
        const int which = threadIdx.x >> 6;             // 0 or 1
        const int j     = threadIdx.x & 63;
        const int row   = r0 + which;
        if (which == 0 || r1 != r0) {
            int id = save_id[row * HIST_DIM + (HIST_DIM - PEN_RANGE) + j];
            size_t off = (size_t)row * VOCAB_DIM + (size_t)id;
            if (off >= lo && off < hi) {
                out[off] = logits[off] * penalty[0];    // idempotent for dups
            }
        }
    }
}

extern "C" void kernel_launch(void* const* d_in, const int* in_sizes, int n_in,
                              void* d_out, int out_size) {
    const float* logits  = (const float*)d_in[0];
    const int*   save_id = (const int*)d_in[1];
    const float* penalty = (const float*)d_in[2];
    float*       out     = (float*)d_out;

    apply_penalty_fused<<<NUM_TILES, THREADS>>>(
        (const float4*)logits, logits, save_id, penalty,
        (float4*)out, out);
}

// round 11
// speedup vs baseline: 1.0007x; 1.0007x over previous
#include <cuda_runtime.h>
#include <cstdint>

// APPLY_PENALTY — final kernel.
// Cost model (validated over 6 variants, R3–R10): dur_us is pinned at the
// compulsory DRAM traffic (131 MB read + 131 MB write = 262 MB) divided by
// the chip's sustained mixed read/write bandwidth (~5.8 TB/s) ≈ 45 us.
// Fusion of the scatter into the copy (R4) bought the only real win
// (49.2 -> 44.7 us); everything else (L2 pinning, v8+policy, TMA, MLP depth)
// was neutral at the DRAM floor.
//
// Problem constants (fixed for this instance):
//   logits:  [B=256, VOCAB=128000] float32
//   save_id: [B=256, HIST=512] int32 (JAX x64 disabled -> int64 decays to int32)
//   penalty_value: [1] float32
//   penalty_range: 64
#define B_DIM      256
#define VOCAB_DIM  128000
#define HIST_DIM   512
#define PEN_RANGE  64

// Row = 32000 float4. Split into 25 segments of 1280 float4 (5120 floats).
#define ROW_F4        32000
#define SEGS_PER_ROW  25
#define SEG_F4        1280
#define SEG_FLOATS    (SEG_F4 * 4)   // 5120
#define THREADS       256
#define F4_PER_THREAD 5              // 256 * 5 = 1280

// Fused copy + penalty fixup, streaming (evict-first) cache hints and
// front-batched loads for per-warp MLP.
__global__ void __launch_bounds__(THREADS)
apply_penalty_fused(const float4* __restrict__ logits4,
                    const float*  __restrict__ logits,
                    const int*    __restrict__ save_id,
                    const float*  __restrict__ penalty,
                    float4* __restrict__ out4,
                    float*  __restrict__ out) {
    const int b   = blockIdx.x;
    const int row = b / SEGS_PER_ROW;
    const int seg = b - row * SEGS_PER_ROW;

    // ---- copy phase: batch all 5 loads, then all 5 stores (streaming) ----
    const size_t base4 = (size_t)row * ROW_F4 + (size_t)seg * SEG_F4 + threadIdx.x;
    float4 v[F4_PER_THREAD];
    #pragma unroll
    for (int i = 0; i < F4_PER_THREAD; i++)
        v[i] = __ldcs(&logits4[base4 + (size_t)i * THREADS]);
    #pragma unroll
    for (int i = 0; i < F4_PER_THREAD; i++)
        __stcs(&out4[base4 + (size_t)i * THREADS], v[i]);

    __syncthreads();   // copy stores ordered before fixup stores (block scope)

    // ---- fixup phase: threads 0..63 check this row's 64 penalized ids ----
    // Only ids landing inside this block's segment are rewritten. The value
    // depends only on the ORIGINAL logit, so duplicate ids are idempotent.
    if (threadIdx.x < PEN_RANGE) {
        const int lo = seg * SEG_FLOATS;
        const int hi = lo + SEG_FLOATS;
        int id = save_id[row * HIST_DIM + (HIST_DIM - PEN_RANGE) + threadIdx.x];
        if (id >= lo && id < hi) {
            const float p = penalty[0];
            size_t off = (size_t)row * VOCAB_DIM + (size_t)id;
            out[off] = logits[off] * p;   // L2-hit read; tiny scattered store
        }
    }
}

extern "C" void kernel_launch(void* const* d_in, const int* in_sizes, int n_in,
                              void* d_out, int out_size) {
    const float* logits  = (const float*)d_in[0];
    const int*   save_id = (const int*)d_in[1];
    const float* penalty = (const float*)d_in[2];
    float*       out     = (float*)d_out;

    const int blocks = B_DIM * SEGS_PER_ROW;   // 6400 blocks x 256 threads
    apply_penalty_fused<<<blocks, THREADS>>>(
        (const float4*)logits, logits, save_id, penalty,
        (float4*)out, out);
}